// round 7
// baseline (speedup 1.0000x reference)
#include <cuda_runtime.h>
#include <cuda_fp16.h>
#include <math.h>

#define NN 100000
#define NE 6400000
#define F1 5     // F_IN
#define F2 5     // F_HID
#define F3 10    // F_OUT

// Scratch (no allocations allowed)
// Packed fp16 gather table: 8 halfs/node = 16B: [f0 f1 f2 f3 f4 degslot pad pad]
__device__ uint4 g_gath16[NN];
// Packed fp16 accumulator: same lane layout, accumulated via red.v4.f16x2
__device__ uint4 g_acc16[NN];
// Full-precision h for the layer-2 self term
__device__ float g_h32[NN * F2];
// Degree saved after pass 1 (acc row gets re-zeroed for pass 2)
__device__ float g_deg32[NN];

__device__ __forceinline__ float sigmoidf_(float z) {
    return 1.0f / (1.0f + __expf(-z));
}

__device__ __forceinline__ unsigned packh2(float a, float b) {
    unsigned lo = __half_as_ushort(__float2half_rn(a));
    unsigned hi = __half_as_ushort(__float2half_rn(b));
    return lo | (hi << 16);
}
__device__ __forceinline__ float loh(unsigned w) {
    return __half2float(__ushort_as_half((unsigned short)(w & 0xFFFF)));
}
__device__ __forceinline__ float hih(unsigned w) {
    return __half2float(__ushort_as_half((unsigned short)(w >> 16)));
}

// 16B load, no L1 allocation (gather table ~1.6MB lives in L2; L1 hit rate is
// low and the fill/evict work competes in the L1tex pipe with the reds).
__device__ __forceinline__ uint4 ldg_na_v4u32(const uint4* p) {
    uint4 r;
    asm volatile("ld.global.nc.L1::no_allocate.v4.u32 {%0, %1, %2, %3}, [%4];"
                 : "=r"(r.x), "=r"(r.y), "=r"(r.z), "=r"(r.w) : "l"(p));
    return r;
}
__device__ __forceinline__ int4 ldg_na_v4s32(const int4* p) {
    int4 r;
    asm volatile("ld.global.nc.L1::no_allocate.v4.s32 {%0, %1, %2, %3}, [%4];"
                 : "=r"(r.x), "=r"(r.y), "=r"(r.z), "=r"(r.w) : "l"(p));
    return r;
}

// Single 16B half-precision vector reduction: 8 half lanes in one LTS op.
__device__ __forceinline__ void red_v4h2(uint4* p, unsigned a, unsigned b,
                                         unsigned c, unsigned d) {
    asm volatile("red.global.add.noftz.v4.f16x2 [%0], {%1, %2, %3, %4};"
                 :: "l"(p), "r"(a), "r"(b), "r"(c), "r"(d) : "memory");
}

// Prep: zero accumulator, quantize x into packed gather table
__global__ void k_prep(const float* __restrict__ x) {
    int v = blockIdx.x * blockDim.x + threadIdx.x;
    if (v >= NN) return;
    const float* xs = x + v * F1;
    unsigned w0 = packh2(xs[0], xs[1]);
    unsigned w1 = packh2(xs[2], xs[3]);
    unsigned w2 = packh2(xs[4], 0.0f);   // deg slot starts at 0
    g_gath16[v] = make_uint4(w0, w1, w2, 0u);
    g_acc16[v]  = make_uint4(0u, 0u, 0u, 0u);
}

// Edge pass: acc16[dst] += gath16[src]. 8 edges/thread, two 4-edge waves.
// One no-allocate LDG.128 + one red.v4.f16x2 per edge.
// DEG=1: also add 1.0h into the deg lane (high half of word 2).
template <int DEG>
__global__ void __launch_bounds__(256) k_edge(const int4* __restrict__ src4,
                                              const int4* __restrict__ dst4) {
    int t = blockIdx.x * blockDim.x + threadIdx.x;
    int base = t * 2;                    // two int4 groups = 8 edges
    if (base >= NE / 4) return;
    const unsigned degbit = DEG ? 0x3C000000u : 0u;   // +1.0h in deg lane
#pragma unroll
    for (int g4 = 0; g4 < 2; g4++) {
        int4 s4 = ldg_na_v4s32(src4 + base + g4);
        int4 d4 = ldg_na_v4s32(dst4 + base + g4);
        int ss[4] = {s4.x, s4.y, s4.z, s4.w};
        int dd[4] = {d4.x, d4.y, d4.z, d4.w};
        uint4 g[4];
#pragma unroll
        for (int k = 0; k < 4; k++) g[k] = ldg_na_v4u32(&g_gath16[ss[k]]);
#pragma unroll
        for (int k = 0; k < 4; k++) {
            red_v4h2(&g_acc16[dd[k]], g[k].x, g[k].y, g[k].z | degbit, g[k].w);
        }
    }
}

// Node pass 1: h = sigmoid(x @ Ws1 + (acc/deg) @ Wn1 + b1)
// Writes: fp32 h (self term of layer 2), packed CENTERED h-0.5 (gather table),
// saved deg, and re-zeroed accumulator.
__global__ void k_node1(const float* __restrict__ x,
                        const float* __restrict__ Ws,
                        const float* __restrict__ Wn,
                        const float* __restrict__ b) {
    int v = blockIdx.x * blockDim.x + threadIdx.x;
    if (v >= NN) return;
    uint4 a = g_acc16[v];
    float deg = hih(a.z);
    float inv = 1.0f / fmaxf(deg, 1.0f);
    float xn[F1] = { loh(a.x) * inv, hih(a.x) * inv,
                     loh(a.y) * inv, hih(a.y) * inv,
                     loh(a.z) * inv };
    float xs[F1];
#pragma unroll
    for (int i = 0; i < F1; i++) xs[i] = x[v * F1 + i];
    float h[F2];
#pragma unroll
    for (int j = 0; j < F2; j++) {
        float z = __ldg(b + j);
#pragma unroll
        for (int i = 0; i < F1; i++) {
            z = fmaf(xs[i], __ldg(Ws + i * F2 + j), z);
            z = fmaf(xn[i], __ldg(Wn + i * F2 + j), z);
        }
        h[j] = sigmoidf_(z);
    }
#pragma unroll
    for (int j = 0; j < F2; j++) g_h32[v * F2 + j] = h[j];
    // Centered h-0.5 keeps fp16 sums small (|sum| ~ sqrt(deg)/4, not deg/2)
    unsigned w0 = packh2(h[0] - 0.5f, h[1] - 0.5f);
    unsigned w1 = packh2(h[2] - 0.5f, h[3] - 0.5f);
    unsigned w2 = packh2(h[4] - 0.5f, 0.0f);
    g_gath16[v] = make_uint4(w0, w1, w2, 0u);
    g_deg32[v]  = deg;
    g_acc16[v]  = make_uint4(0u, 0u, 0u, 0u);
}

// Node pass 2: out = sigmoid(h @ Ws2 + (acc_c/deg + 0.5) @ Wn2 + b2)
__global__ void k_node2(float* __restrict__ out,
                        const float* __restrict__ Ws,
                        const float* __restrict__ Wn,
                        const float* __restrict__ b) {
    int v = blockIdx.x * blockDim.x + threadIdx.x;
    if (v >= NN) return;
    uint4 a = g_acc16[v];
    float deg = g_deg32[v];
    float inv = 1.0f / fmaxf(deg, 1.0f);
    // De-center: mean(h) = mean(h-0.5) + 0.5  (only where deg>0; deg==0 must give 0)
    float half_off = (deg > 0.0f) ? 0.5f : 0.0f;
    float hn[F2] = { loh(a.x) * inv + half_off, hih(a.x) * inv + half_off,
                     loh(a.y) * inv + half_off, hih(a.y) * inv + half_off,
                     loh(a.z) * inv + half_off };
    float hs[F2];
#pragma unroll
    for (int i = 0; i < F2; i++) hs[i] = g_h32[v * F2 + i];
#pragma unroll
    for (int j = 0; j < F3; j++) {
        float z = __ldg(b + j);
#pragma unroll
        for (int i = 0; i < F2; i++) {
            z = fmaf(hs[i], __ldg(Ws + i * F3 + j), z);
            z = fmaf(hn[i], __ldg(Wn + i * F3 + j), z);
        }
        out[v * F3 + j] = sigmoidf_(z);
    }
}

extern "C" void kernel_launch(void* const* d_in, const int* in_sizes, int n_in,
                              void* d_out, int out_size) {
    const float* x   = (const float*)d_in[0];
    const int*   src = (const int*)d_in[1];
    const int*   dst = (const int*)d_in[2];
    const float* Ws1 = (const float*)d_in[3];
    const float* Wn1 = (const float*)d_in[4];
    const float* b1  = (const float*)d_in[5];
    const float* Ws2 = (const float*)d_in[6];
    const float* Wn2 = (const float*)d_in[7];
    const float* b2  = (const float*)d_in[8];
    float* out = (float*)d_out;

    const int VB = 256;
    int vgrid = (NN + VB - 1) / VB;

    const int EB = 256;
    int egrid = (NE / 8 + EB - 1) / EB;   // 8 edges per thread

    k_prep<<<vgrid, VB>>>(x);
    k_edge<1><<<egrid, EB>>>((const int4*)src, (const int4*)dst);
    k_node1<<<vgrid, VB>>>(x, Ws1, Wn1, b1);
    k_edge<0><<<egrid, EB>>>((const int4*)src, (const int4*)dst);
    k_node2<<<vgrid, VB>>>(out, Ws2, Wn2, b2);
}

// round 8
// speedup vs baseline: 1.0520x; 1.0520x over previous
#include <cuda_runtime.h>
#include <cuda_fp16.h>
#include <math.h>

#define NN 100000
#define NE 6400000
#define F1 5     // F_IN
#define F2 5     // F_HID
#define F3 10    // F_OUT

// Scratch (no allocations allowed)
// Packed fp16 gather table: 8 halfs/node = 16B: [f0 f1 f2 f3 f4 degslot pad pad]
__device__ uint4 g_gath16[NN];
// Packed fp16 accumulator: same lane layout, accumulated via red.v4.f16x2
__device__ uint4 g_acc16[NN];
// Full-precision h for the layer-2 self term
__device__ float g_h32[NN * F2];
// Degree saved after pass 1 (acc row gets re-zeroed for pass 2)
__device__ float g_deg32[NN];

__device__ __forceinline__ float sigmoidf_(float z) {
    return 1.0f / (1.0f + __expf(-z));
}

__device__ __forceinline__ unsigned packh2(float a, float b) {
    unsigned lo = __half_as_ushort(__float2half_rn(a));
    unsigned hi = __half_as_ushort(__float2half_rn(b));
    return lo | (hi << 16);
}
__device__ __forceinline__ float loh(unsigned w) {
    return __half2float(__ushort_as_half((unsigned short)(w & 0xFFFF)));
}
__device__ __forceinline__ float hih(unsigned w) {
    return __half2float(__ushort_as_half((unsigned short)(w >> 16)));
}

// Gather-table load: high reuse (~64x/node per pass) -> protect in L1.
__device__ __forceinline__ uint4 ldg_el_v4u32(const uint4* p) {
    uint4 r;
    asm volatile("ld.global.nc.L1::evict_last.v4.u32 {%0, %1, %2, %3}, [%4];"
                 : "=r"(r.x), "=r"(r.y), "=r"(r.z), "=r"(r.w) : "l"(p));
    return r;
}
// Index-stream load: zero reuse -> evict first, don't displace table lines.
__device__ __forceinline__ int4 ldg_ef_v4s32(const int4* p) {
    int4 r;
    asm volatile("ld.global.nc.L1::evict_first.v4.s32 {%0, %1, %2, %3}, [%4];"
                 : "=r"(r.x), "=r"(r.y), "=r"(r.z), "=r"(r.w) : "l"(p));
    return r;
}

// Single 16B half-precision vector reduction: 8 half lanes in one LTS op.
__device__ __forceinline__ void red_v4h2(uint4* p, unsigned a, unsigned b,
                                         unsigned c, unsigned d) {
    asm volatile("red.global.add.noftz.v4.f16x2 [%0], {%1, %2, %3, %4};"
                 :: "l"(p), "r"(a), "r"(b), "r"(c), "r"(d) : "memory");
}

// Prep: zero accumulator, quantize x into packed gather table
__global__ void k_prep(const float* __restrict__ x) {
    int v = blockIdx.x * blockDim.x + threadIdx.x;
    if (v >= NN) return;
    const float* xs = x + v * F1;
    unsigned w0 = packh2(xs[0], xs[1]);
    unsigned w1 = packh2(xs[2], xs[3]);
    unsigned w2 = packh2(xs[4], 0.0f);   // deg slot starts at 0
    g_gath16[v] = make_uint4(w0, w1, w2, 0u);
    g_acc16[v]  = make_uint4(0u, 0u, 0u, 0u);
}

// Edge pass: acc16[dst] += gath16[src], one LDG.128 + one red.v4.f16x2 per edge.
// 4 edges per thread via int4 index loads.
// DEG=1: also add 1.0h into the deg lane (high half of word 2).
template <int DEG>
__global__ void __launch_bounds__(256) k_edge(const int4* __restrict__ src4,
                                              const int4* __restrict__ dst4) {
    int t = blockIdx.x * blockDim.x + threadIdx.x;
    if (t >= NE / 4) return;
    int4 s4 = ldg_ef_v4s32(src4 + t);
    int4 d4 = ldg_ef_v4s32(dst4 + t);
    int ss[4] = {s4.x, s4.y, s4.z, s4.w};
    int dd[4] = {d4.x, d4.y, d4.z, d4.w};
    const unsigned degbit = DEG ? 0x3C000000u : 0u;   // +1.0h in deg lane
    uint4 g[4];
#pragma unroll
    for (int k = 0; k < 4; k++) g[k] = ldg_el_v4u32(&g_gath16[ss[k]]);
#pragma unroll
    for (int k = 0; k < 4; k++) {
        red_v4h2(&g_acc16[dd[k]], g[k].x, g[k].y, g[k].z | degbit, g[k].w);
    }
}

// Node pass 1: h = sigmoid(x @ Ws1 + (acc/deg) @ Wn1 + b1)
// Writes: fp32 h (self term of layer 2), packed CENTERED h-0.5 (gather table),
// saved deg, and re-zeroed accumulator.
__global__ void k_node1(const float* __restrict__ x,
                        const float* __restrict__ Ws,
                        const float* __restrict__ Wn,
                        const float* __restrict__ b) {
    int v = blockIdx.x * blockDim.x + threadIdx.x;
    if (v >= NN) return;
    uint4 a = g_acc16[v];
    float deg = hih(a.z);
    float inv = 1.0f / fmaxf(deg, 1.0f);
    float xn[F1] = { loh(a.x) * inv, hih(a.x) * inv,
                     loh(a.y) * inv, hih(a.y) * inv,
                     loh(a.z) * inv };
    float xs[F1];
#pragma unroll
    for (int i = 0; i < F1; i++) xs[i] = x[v * F1 + i];
    float h[F2];
#pragma unroll
    for (int j = 0; j < F2; j++) {
        float z = __ldg(b + j);
#pragma unroll
        for (int i = 0; i < F1; i++) {
            z = fmaf(xs[i], __ldg(Ws + i * F2 + j), z);
            z = fmaf(xn[i], __ldg(Wn + i * F2 + j), z);
        }
        h[j] = sigmoidf_(z);
    }
#pragma unroll
    for (int j = 0; j < F2; j++) g_h32[v * F2 + j] = h[j];
    // Centered h-0.5 keeps fp16 sums small (|sum| ~ sqrt(deg)/4, not deg/2)
    unsigned w0 = packh2(h[0] - 0.5f, h[1] - 0.5f);
    unsigned w1 = packh2(h[2] - 0.5f, h[3] - 0.5f);
    unsigned w2 = packh2(h[4] - 0.5f, 0.0f);
    g_gath16[v] = make_uint4(w0, w1, w2, 0u);
    g_deg32[v]  = deg;
    g_acc16[v]  = make_uint4(0u, 0u, 0u, 0u);
}

// Node pass 2: out = sigmoid(h @ Ws2 + (acc_c/deg + 0.5) @ Wn2 + b2)
__global__ void k_node2(float* __restrict__ out,
                        const float* __restrict__ Ws,
                        const float* __restrict__ Wn,
                        const float* __restrict__ b) {
    int v = blockIdx.x * blockDim.x + threadIdx.x;
    if (v >= NN) return;
    uint4 a = g_acc16[v];
    float deg = g_deg32[v];
    float inv = 1.0f / fmaxf(deg, 1.0f);
    // De-center: mean(h) = mean(h-0.5) + 0.5  (only where deg>0; deg==0 must give 0)
    float half_off = (deg > 0.0f) ? 0.5f : 0.0f;
    float hn[F2] = { loh(a.x) * inv + half_off, hih(a.x) * inv + half_off,
                     loh(a.y) * inv + half_off, hih(a.y) * inv + half_off,
                     loh(a.z) * inv + half_off };
    float hs[F2];
#pragma unroll
    for (int i = 0; i < F2; i++) hs[i] = g_h32[v * F2 + i];
#pragma unroll
    for (int j = 0; j < F3; j++) {
        float z = __ldg(b + j);
#pragma unroll
        for (int i = 0; i < F2; i++) {
            z = fmaf(hs[i], __ldg(Ws + i * F3 + j), z);
            z = fmaf(hn[i], __ldg(Wn + i * F3 + j), z);
        }
        out[v * F3 + j] = sigmoidf_(z);
    }
}

extern "C" void kernel_launch(void* const* d_in, const int* in_sizes, int n_in,
                              void* d_out, int out_size) {
    const float* x   = (const float*)d_in[0];
    const int*   src = (const int*)d_in[1];
    const int*   dst = (const int*)d_in[2];
    const float* Ws1 = (const float*)d_in[3];
    const float* Wn1 = (const float*)d_in[4];
    const float* b1  = (const float*)d_in[5];
    const float* Ws2 = (const float*)d_in[6];
    const float* Wn2 = (const float*)d_in[7];
    const float* b2  = (const float*)d_in[8];
    float* out = (float*)d_out;

    const int VB = 256;
    int vgrid = (NN + VB - 1) / VB;

    const int EB = 256;
    int egrid = (NE / 4 + EB - 1) / EB;   // 4 edges per thread

    k_prep<<<vgrid, VB>>>(x);
    k_edge<1><<<egrid, EB>>>((const int4*)src, (const int4*)dst);
    k_node1<<<vgrid, VB>>>(x, Ws1, Wn1, b1);
    k_edge<0><<<egrid, EB>>>((const int4*)src, (const int4*)dst);
    k_node2<<<vgrid, VB>>>(out, Ws2, Wn2, b2);
}